// round 17
// baseline (speedup 1.0000x reference)
#include <cuda_runtime.h>
#include <cuda_bf16.h>
#include <cstdint>

// ---------------------------------------------------------------------------
// GraphSAGE 2-layer (mean aggregation), N=100000 nodes, F: 27 -> 128 -> 64.
//
//   k_init  : detect edge dtype (block 0) + zero g_cnt
//   k_bucket: direct padded-CSR build (one pass, no count/scan)
//   k_agg1  : agg1[n,27] = mean_{dst=n} x[src]
//   k_mma   : persistent warp-MMA kernel, 512 threads, four 128-thread
//             warpgroups (wm = wid>>2: one warp per group per SMSP).
//             R17 CHANGE: term-major MMA ordering.  The 3 split-bf16 terms
//             (ah*bh, ah*bl, al*bh) previously accumulated back-to-back into
//             the same register (asm volatile => SASS order) -- a pure RAW
//             chain.  Now B frags are preloaded and each term is a pass of 4
//             independent accumulators: same-acc writes are 4 MMAs apart.
//   k_agg2  : out = mean_{dst} p[src] + b2 + r
// ---------------------------------------------------------------------------

#define NN    100000
#define CAP   128                      // padded CSR capacity per node
#define NT2   ((NN + 127) / 128)       // 782 tiles of 128 nodes
#define MGRID 148                      // persistent grid (1 block/SM)

static __device__ int   g_is64;
static __device__ int   g_cnt[NN];
static __device__ int   g_csr[NN * CAP];     // 51.2 MB padded CSR
static __device__ float g_agg1[NN * 28];     // padded row: [27]=0
static __device__ float g_p[NN * 64];
static __device__ float g_r[NN * 64];

// ---------------- warp-MMA helpers (all sm_80-base ISA) ---------------------

__device__ __forceinline__ uint32_t smem_u32(const void* p) {
    uint32_t a;
    asm("{ .reg .u64 t; cvta.to.shared.u64 t, %1; cvt.u32.u64 %0, t; }"
        : "=r"(a) : "l"(p));
    return a;
}

__device__ __forceinline__ void ldsm4(uint32_t* r, uint32_t a) {
    asm volatile("ldmatrix.sync.aligned.m8n8.x4.shared.b16 {%0,%1,%2,%3}, [%4];"
        : "=r"(r[0]), "=r"(r[1]), "=r"(r[2]), "=r"(r[3]) : "r"(a));
}
__device__ __forceinline__ void ldsm2(uint32_t* r, uint32_t a) {
    asm volatile("ldmatrix.sync.aligned.m8n8.x2.shared.b16 {%0,%1}, [%2];"
        : "=r"(r[0]), "=r"(r[1]) : "r"(a));
}
// D += A(16x16,row) * B(16x8,col)  -- bf16 in, fp32 accum
__device__ __forceinline__ void mma16816(float* c, const uint32_t* a, const uint32_t* b) {
    asm volatile(
        "mma.sync.aligned.m16n8k16.row.col.f32.bf16.bf16.f32 "
        "{%0,%1,%2,%3}, {%4,%5,%6,%7}, {%8,%9}, {%0,%1,%2,%3};"
        : "+f"(c[0]), "+f"(c[1]), "+f"(c[2]), "+f"(c[3])
        : "r"(a[0]), "r"(a[1]), "r"(a[2]), "r"(a[3]), "r"(b[0]), "r"(b[1]));
}

// group barrier: the 4 warps sharing wm (128 threads), ids 1..4
__device__ __forceinline__ void barg(int wm) {
    asm volatile("bar.sync %0, 128;" :: "r"(wm + 1) : "memory");
}

// split v into bf16 hi + bf16 residual, packed as bf16x2 words (v0=low half)
__device__ __forceinline__ void split2(float v0, float v1, uint32_t& hi, uint32_t& lo) {
    __nv_bfloat16 h0 = __float2bfloat16(v0);
    __nv_bfloat16 h1 = __float2bfloat16(v1);
    __nv_bfloat162 H = __halves2bfloat162(h0, h1);
    __nv_bfloat162 L = __halves2bfloat162(
        __float2bfloat16(v0 - __bfloat162float(h0)),
        __float2bfloat16(v1 - __bfloat162float(h1)));
    hi = *reinterpret_cast<uint32_t*>(&H);
    lo = *reinterpret_cast<uint32_t*>(&L);
}

// ---------------- graph kernels ---------------------------------------------

__device__ __forceinline__ int eidx(const int* __restrict__ e, int elem, int is64) {
    return is64 ? e[2 * elem] : e[elem];
}

__global__ void k_init(const int* __restrict__ e) {
    if (blockIdx.x == 0) {
        __shared__ int s;
        if (threadIdx.x == 0) s = 0;
        __syncthreads();
        if (threadIdx.x < 64 && e[2 * threadIdx.x + 1] != 0) atomicOr(&s, 1);
        __syncthreads();
        if (threadIdx.x == 0) g_is64 = (s == 0);
    }
    int i = blockIdx.x * blockDim.x + threadIdx.x;
    if (i < NN) g_cnt[i] = 0;
}

__global__ void k_bucket(const int* __restrict__ e, int E) {
    int i = blockIdx.x * blockDim.x + threadIdx.x;
    if (i >= E) return;
    int is64 = g_is64;
    int s = eidx(e, i, is64);
    int d = eidx(e, E + i, is64);
    int pos = atomicAdd(&g_cnt[d], 1);
    if (pos < CAP) g_csr[d * CAP + pos] = s;
}

__global__ void k_agg1(const float* __restrict__ x) {
    int w    = (blockIdx.x * blockDim.x + threadIdx.x) >> 5;
    int lane = threadIdx.x & 31;
    if (w >= NN) return;
    int cnt = g_cnt[w];
    int cc  = (cnt < CAP) ? cnt : CAP;
    int start = w * CAP;
    int lf = (lane < 27) ? lane : 0;
    float a0 = 0.f, a1 = 0.f;
    int k = 0;
    for (; k + 8 <= cc; k += 8) {
        int s0 = g_csr[start + k],     s1 = g_csr[start + k + 1];
        int s2 = g_csr[start + k + 2], s3 = g_csr[start + k + 3];
        int s4 = g_csr[start + k + 4], s5 = g_csr[start + k + 5];
        int s6 = g_csr[start + k + 6], s7 = g_csr[start + k + 7];
        float v0 = x[s0 * 27 + lf], v1 = x[s1 * 27 + lf];
        float v2 = x[s2 * 27 + lf], v3 = x[s3 * 27 + lf];
        float v4 = x[s4 * 27 + lf], v5 = x[s5 * 27 + lf];
        float v6 = x[s6 * 27 + lf], v7 = x[s7 * 27 + lf];
        a0 += (v0 + v1) + (v2 + v3);
        a1 += (v4 + v5) + (v6 + v7);
    }
    for (; k < cc; k++) a0 += x[g_csr[start + k] * 27 + lf];
    a0 += a1;
    float inv = 1.f / (float)(cnt > 0 ? cnt : 1);
    if (lane < 28) g_agg1[w * 28 + lane] = (lane < 27) ? a0 * inv : 0.f;
}

// ---------------- persistent warp-MMA fused GEMM (4 warpgroups) -------------
#define PITCH1 144                       // 64 bf16 = 128B + 16B pad
#define PITCH2 272                       // 128 bf16 = 256B + 16B pad
#define OFF_BIAS 0                       // 128 floats
#define OFF_B1H  512
#define OFF_B1L  (OFF_B1H + 128 * PITCH1)
#define OFF_A1H  (OFF_B1L + 128 * PITCH1)
#define OFF_A1L  (OFF_A1H + 128 * PITCH1)
#define OFF_B2H  (OFF_A1L + 128 * PITCH1)
#define OFF_B2L  (OFF_B2H + 128 * PITCH2)
#define OFF_A2H  (OFF_B2L + 128 * PITCH2)
#define OFF_A2L  (OFF_A2H + 128 * PITCH2)
#define SMEM_TOT (OFF_A2L + 128 * PITCH2)   // 213504 B

// stage A1 strip rows [wm*32, wm*32+32) of tile n0 (group-local, no barrier)
__device__ __forceinline__ void stage_a1_strip(char* sm, int n0, int wm, int gtid,
                                               const float* __restrict__ x) {
    int rbase = wm * 32;
    for (int idx = gtid; idx < 32 * 32; idx += 128) {
        int rr = rbase + (idx >> 5);
        int k = (idx & 31) * 2;
        int n = n0 + rr;
        float v0 = 0.f, v1 = 0.f;
        if (n < NN) {
            v0 = (k < 28) ? g_agg1[n * 28 + k]
                          : ((k < 55) ? x[n * 27 + (k - 28)] : 0.f);
            int k1 = k + 1;
            v1 = (k1 < 28) ? g_agg1[n * 28 + k1]
                           : ((k1 < 55) ? x[n * 27 + (k1 - 28)] : 0.f);
        }
        uint32_t hi, lo; split2(v0, v1, hi, lo);
        uint32_t off = (uint32_t)(rr * PITCH1 + k * 2);
        *reinterpret_cast<uint32_t*>(sm + OFF_A1H + off) = hi;
        *reinterpret_cast<uint32_t*>(sm + OFF_A1L + off) = lo;
    }
}

__global__ void __launch_bounds__(512, 1) k_mma(
    const float* __restrict__ x, const float* __restrict__ W1l,
    const float* __restrict__ b1, const float* __restrict__ W1r,
    const float* __restrict__ W2l, const float* __restrict__ W2r) {
    extern __shared__ char sm[];
    uint32_t sb = smem_u32(sm);
    int tid  = threadIdx.x;
    int wid  = tid >> 5;
    int lane = tid & 31;
    int wm   = wid >> 2;                 // warpgroup / m strip
    int wn   = wid & 3;                  // n strip within group
    int gtid = wn * 32 + lane;           // thread index within the 128-thr group
    int g    = lane >> 2;                // fragment group row
    int tig  = lane & 3;                 // thread-in-group (col pair)
    float* sBias = reinterpret_cast<float*>(sm + OFF_BIAS);

    uint32_t aoff1 = (uint32_t)((lane & 15) * PITCH1 + (lane >> 4) * 16);
    uint32_t boff1 = (uint32_t)((lane & 7) * PITCH1 + ((lane >> 3) & 1) * 16);
    uint32_t aoff2 = (uint32_t)((lane & 15) * PITCH2 + (lane >> 4) * 16);
    uint32_t boff2 = (uint32_t)((lane & 7) * PITCH2 + ((lane >> 3) & 1) * 16);

    // ---- stage weights (split bf16) once per block -------------------------
    for (int idx = tid; idx < 128 * 32; idx += 512) {
        int n = idx >> 5, k = (idx & 31) * 2;
        float v0 = 0.f, v1 = 0.f;
        if (k < 27) v0 = W1l[k * 128 + n];
        else if (k >= 28 && k < 55) v0 = W1r[(k - 28) * 128 + n];
        int k1 = k + 1;
        if (k1 < 27) v1 = W1l[k1 * 128 + n];
        else if (k1 >= 28 && k1 < 55) v1 = W1r[(k1 - 28) * 128 + n];
        uint32_t hi, lo; split2(v0, v1, hi, lo);
        uint32_t off = (uint32_t)(n * PITCH1 + k * 2);
        *reinterpret_cast<uint32_t*>(sm + OFF_B1H + off) = hi;
        *reinterpret_cast<uint32_t*>(sm + OFF_B1L + off) = lo;
    }
    for (int idx = tid; idx < 128 * 64; idx += 512) {
        int n = idx >> 6, k = (idx & 63) * 2;
        float v0 = (n < 64) ? W2l[k * 64 + n] : W2r[k * 64 + (n - 64)];
        float v1 = (n < 64) ? W2l[(k + 1) * 64 + n] : W2r[(k + 1) * 64 + (n - 64)];
        uint32_t hi, lo; split2(v0, v1, hi, lo);
        uint32_t off = (uint32_t)(n * PITCH2 + k * 2);
        *reinterpret_cast<uint32_t*>(sm + OFF_B2H + off) = hi;
        *reinterpret_cast<uint32_t*>(sm + OFF_B2L + off) = lo;
    }
    if (tid < 128) sBias[tid] = b1[tid];
    __syncthreads();                     // B / bias visible to all groups

    // ---- prologue: each group stages its strip of the first tile -----------
    stage_a1_strip(sm, blockIdx.x * 128, wm, gtid, x);
    barg(wm);

    for (int tile = blockIdx.x; tile < NT2; tile += MGRID) {
        int n0 = tile * 128;

        // ---- phase 1: acc = A1(strip) @ B1 (K=64, 3-term, term-major) ------
        float acc[2][4][4];
#pragma unroll
        for (int mt = 0; mt < 2; mt++)
#pragma unroll
            for (int nt = 0; nt < 4; nt++)
#pragma unroll
                for (int q = 0; q < 4; q++) acc[mt][nt][q] = 0.f;

#pragma unroll
        for (int ks = 0; ks < 4; ks++) {
            uint32_t bh[4][2], bl[4][2];
#pragma unroll
            for (int nt = 0; nt < 4; nt++) {
                uint32_t bb = sb + OFF_B1H + (uint32_t)((wn * 32 + nt * 8) * PITCH1 + ks * 32) + boff1;
                ldsm2(bh[nt], bb);
                ldsm2(bl[nt], bb + (OFF_B1L - OFF_B1H));
            }
#pragma unroll
            for (int mt = 0; mt < 2; mt++) {
                uint32_t ah[4], al[4];
                uint32_t ab = sb + OFF_A1H + (uint32_t)((wm * 32 + mt * 16) * PITCH1 + ks * 32) + aoff1;
                ldsm4(ah, ab);
                ldsm4(al, ab + (OFF_A1L - OFF_A1H));
                // term-major: each pass = 4 independent accumulators
#pragma unroll
                for (int nt = 0; nt < 4; nt++) mma16816(acc[mt][nt], ah, bh[nt]);
#pragma unroll
                for (int nt = 0; nt < 4; nt++) mma16816(acc[mt][nt], ah, bl[nt]);
#pragma unroll
                for (int nt = 0; nt < 4; nt++) mma16816(acc[mt][nt], al, bh[nt]);
            }
        }

        // ---- epilogue 1: h = relu(acc + b1) -> split bf16 -> A2(strip) -----
#pragma unroll
        for (int mt = 0; mt < 2; mt++) {
#pragma unroll
            for (int nt = 0; nt < 4; nt++) {
                int c  = wn * 32 + nt * 8 + tig * 2;
                float bv0 = sBias[c], bv1 = sBias[c + 1];
                int r0 = wm * 32 + mt * 16 + g;
                float v00 = fmaxf(acc[mt][nt][0] + bv0, 0.f);
                float v01 = fmaxf(acc[mt][nt][1] + bv1, 0.f);
                float v10 = fmaxf(acc[mt][nt][2] + bv0, 0.f);
                float v11 = fmaxf(acc[mt][nt][3] + bv1, 0.f);
                uint32_t hi, lo;
                uint32_t off0 = (uint32_t)(r0 * PITCH2 + c * 2);
                split2(v00, v01, hi, lo);
                *reinterpret_cast<uint32_t*>(sm + OFF_A2H + off0) = hi;
                *reinterpret_cast<uint32_t*>(sm + OFF_A2L + off0) = lo;
                uint32_t off1 = (uint32_t)((r0 + 8) * PITCH2 + c * 2);
                split2(v10, v11, hi, lo);
                *reinterpret_cast<uint32_t*>(sm + OFF_A2H + off1) = hi;
                *reinterpret_cast<uint32_t*>(sm + OFF_A2L + off1) = lo;
            }
        }
        barg(wm);          // A2 strip complete within group; A1 strip now dead

        // ---- pipelined staging: A1 strip for tile+MGRID (overlaps mma2) ----
        if (tile + MGRID < NT2)
            stage_a1_strip(sm, (tile + MGRID) * 128, wm, gtid, x);

        // ---- phase 2: acc = A2(strip) @ B2 (K=128, 3-term, term-major) -----
#pragma unroll
        for (int mt = 0; mt < 2; mt++)
#pragma unroll
            for (int nt = 0; nt < 4; nt++)
#pragma unroll
                for (int q = 0; q < 4; q++) acc[mt][nt][q] = 0.f;

#pragma unroll
        for (int ks = 0; ks < 8; ks++) {
            uint32_t bh[4][2], bl[4][2];
#pragma unroll
            for (int nt = 0; nt < 4; nt++) {
                uint32_t bb = sb + OFF_B2H + (uint32_t)((wn * 32 + nt * 8) * PITCH2 + ks * 32) + boff2;
                ldsm2(bh[nt], bb);
                ldsm2(bl[nt], bb + (OFF_B2L - OFF_B2H));
            }
#pragma unroll
            for (int mt = 0; mt < 2; mt++) {
                uint32_t ah[4], al[4];
                uint32_t ab = sb + OFF_A2H + (uint32_t)((wm * 32 + mt * 16) * PITCH2 + ks * 32) + aoff2;
                ldsm4(ah, ab);
                ldsm4(al, ab + (OFF_A2L - OFF_A2H));
#pragma unroll
                for (int nt = 0; nt < 4; nt++) mma16816(acc[mt][nt], ah, bh[nt]);
#pragma unroll
                for (int nt = 0; nt < 4; nt++) mma16816(acc[mt][nt], ah, bl[nt]);
#pragma unroll
                for (int nt = 0; nt < 4; nt++) mma16816(acc[mt][nt], al, bh[nt]);
            }
        }

        // ---- epilogue 2: fragments -> g_p (cols 0-63) / g_r (64-127) -------
        {
            float* base = (wn >= 2) ? g_r : g_p;
            int cbase = (wn & 1) * 32;
#pragma unroll
            for (int mt = 0; mt < 2; mt++) {
#pragma unroll
                for (int nt = 0; nt < 4; nt++) {
                    int cc = cbase + nt * 8 + tig * 2;     // col within 64
                    int r0 = n0 + wm * 32 + mt * 16 + g;
                    if (r0 < NN) {
                        float2 v = make_float2(acc[mt][nt][0], acc[mt][nt][1]);
                        *reinterpret_cast<float2*>(base + (size_t)r0 * 64 + cc) = v;
                    }
                    if (r0 + 8 < NN) {
                        float2 v = make_float2(acc[mt][nt][2], acc[mt][nt][3]);
                        *reinterpret_cast<float2*>(base + (size_t)(r0 + 8) * 64 + cc) = v;
                    }
                }
            }
        }
        barg(wm);   // A1(next) strip writes + A2 strip reads done within group
    }
}

// ---------------- layer-2 aggregation + epilogue ----------------------------
__global__ void k_agg2(const float* __restrict__ b2, float* __restrict__ out) {
    int w    = (blockIdx.x * blockDim.x + threadIdx.x) >> 5;
    int lane = threadIdx.x & 31;
    if (w >= NN) return;
    int cnt = g_cnt[w];
    int cc  = (cnt < CAP) ? cnt : CAP;
    int start = w * CAP;
    const float2* __restrict__ p2 = reinterpret_cast<const float2*>(g_p);
    float ax = 0.f, ay = 0.f, bx = 0.f, by = 0.f;
    int k = 0;
    for (; k + 4 <= cc; k += 4) {
        int s0 = g_csr[start + k],     s1 = g_csr[start + k + 1];
        int s2 = g_csr[start + k + 2], s3 = g_csr[start + k + 3];
        float2 v0 = p2[s0 * 32 + lane];
        float2 v1 = p2[s1 * 32 + lane];
        float2 v2 = p2[s2 * 32 + lane];
        float2 v3 = p2[s3 * 32 + lane];
        ax += v0.x + v1.x;  ay += v0.y + v1.y;
        bx += v2.x + v3.x;  by += v2.y + v3.y;
    }
    for (; k < cc; k++) {
        float2 v0 = p2[g_csr[start + k] * 32 + lane];
        ax += v0.x; ay += v0.y;
    }
    ax += bx; ay += by;
    float inv = 1.f / (float)(cnt > 0 ? cnt : 1);
    const float2* __restrict__ b22 = reinterpret_cast<const float2*>(b2);
    const float2* __restrict__ r2  = reinterpret_cast<const float2*>(g_r);
    float2 bv = b22[lane];
    float2 rv = r2[w * 32 + lane];
    float2 o;
    o.x = ax * inv + bv.x + rv.x;
    o.y = ay * inv + bv.y + rv.y;
    reinterpret_cast<float2*>(out)[w * 32 + lane] = o;
}

extern "C" void kernel_launch(void* const* d_in, const int* in_sizes, int n_in,
                              void* d_out, int out_size) {
    const float* x   = (const float*)d_in[0];
    const int*   e   = (const int*)d_in[1];
    const float* W1l = (const float*)d_in[2];
    const float* b1  = (const float*)d_in[3];
    const float* W1r = (const float*)d_in[4];
    const float* W2l = (const float*)d_in[5];
    const float* b2  = (const float*)d_in[6];
    const float* W2r = (const float*)d_in[7];
    float* out = (float*)d_out;
    int E = in_sizes[1] / 2;

    cudaFuncSetAttribute(k_mma, cudaFuncAttributeMaxDynamicSharedMemorySize, SMEM_TOT);

    k_init  <<<(NN + 255) / 256, 256>>>(e);
    k_bucket<<<(E + 255) / 256, 256>>>(e, E);
    k_agg1  <<<(NN + 7) / 8, 256>>>(x);
    k_mma   <<<MGRID, 512, SMEM_TOT>>>(x, W1l, b1, W1r, W2l, W2r);
    k_agg2  <<<(NN + 7) / 8, 256>>>(b2, out);
}